// round 14
// baseline (speedup 1.0000x reference)
#include <cuda_runtime.h>
#include <cuda_bf16.h>
#include <stdint.h>

// Problem constants (fixed by the dataset)
#define NN 100000
#define CC 64
#define EE 1200000
#define GG 256
#define EPS 1e-5f

typedef unsigned long long u64;

#define FLAG_AGG (1ULL << 62)
#define FLAG_PRE (2ULL << 62)
#define VALMASK  ((1ULL << 62) - 1ULL)

// ---------------------------------------------------------------------------
// Scratch (device globals; loader zero-initialized; each call re-zeroes what
// it dirties AFTER last use so the graph stays deterministic).
// ---------------------------------------------------------------------------
__device__ __align__(16) float g_h[NN * CC];      // SAGE output
__device__ __align__(16) float g_mean[GG * CC];   // per-graph mean
__device__ __align__(16) float g_rstd[GG * CC];   // per-graph rsqrt(var+eps)
__device__ __align__(16) float g_stat[GG * 128];  // per-graph partial sum[64]|sq[64]

__device__ __align__(16) int g_cnt[NN];           // in-degree counts (zeroed by kD)
__device__ __align__(16) int g_off[NN + 1];       // CSR offsets
__device__ __align__(16) int g_cur[NN];           // placement cursors
__device__ __align__(16) int g_srcidx[EE];        // CSR: src node per slot
__device__ int g_k2b_ctr[GG];                     // last-block counters (zeroed by kD)
__device__ volatile u64 g_scanstate[512];         // lookback state (zeroed by kD)

__device__ __forceinline__ void red_add_v4(float* addr, float4 v)
{
    asm volatile("red.global.add.v4.f32 [%0], {%1, %2, %3, %4};"
                 :: "l"(addr), "f"(v.x), "f"(v.y), "f"(v.z), "f"(v.w)
                 : "memory");
}

// ---------------------------------------------------------------------------
// kB: histogram of in-degree. 4 edges/thread.
// ---------------------------------------------------------------------------
__global__ void kB_hist(const int* __restrict__ ei, int E)
{
    int base = (blockIdx.x * blockDim.x + threadIdx.x) * 4;
#pragma unroll
    for (int u = 0; u < 4; u++) {
        int e = base + u;
        if (e < E) atomicAdd(&g_cnt[ei[E + e]], 1);
    }
}

// ---------------------------------------------------------------------------
// kScan: single-pass exclusive scan of g_cnt -> g_off[N+1], g_cur
// (decoupled lookback, warp-parallel 32-wide windows)
// ---------------------------------------------------------------------------
__global__ __launch_bounds__(256) void kScan(int N)
{
    int b = blockIdx.x;
    int i = b * 256 + threadIdx.x;
    int lane = threadIdx.x & 31, w = threadIdx.x >> 5;

    int v = (i < N) ? g_cnt[i] : 0;
    int s = v;
#pragma unroll
    for (int o = 1; o < 32; o <<= 1) {
        int t = __shfl_up_sync(0xffffffffu, s, o);
        if (lane >= o) s += t;
    }
    __shared__ int wsum[8], woff[8], sbtot;
    __shared__ u64 sprefix;
    if (lane == 31) wsum[w] = s;
    __syncthreads();
    if (threadIdx.x == 0) {
        int acc = 0;
#pragma unroll
        for (int k = 0; k < 8; k++) { woff[k] = acc; acc += wsum[k]; }
        sbtot = acc;
        __threadfence();
        g_scanstate[b] = (b == 0 ? FLAG_PRE : FLAG_AGG) | (u64)acc;
        if (b == 0) sprefix = 0ULL;
    }
    __syncthreads();
    int incl = s + woff[w];
    int total = sbtot;

    if (b > 0 && w == 0) {
        long long run = 0;
        int base = b - 1;
        bool done = false;
        while (!done) {
            int idx = base - lane;
            u64 st = FLAG_PRE;
            if (idx >= 0) {
                do { st = g_scanstate[idx]; } while ((st >> 62) == 0ULL);
            }
            unsigned pre = __ballot_sync(0xffffffffu, (st >> 62) == 2ULL);
            long long val = (long long)(st & VALMASK);
            long long contrib;
            if (pre) {
                int firstpre = __ffs(pre) - 1;
                contrib = (lane <= firstpre) ? val : 0;
                done = true;
            } else {
                contrib = val;
            }
#pragma unroll
            for (int o = 16; o > 0; o >>= 1)
                contrib += __shfl_down_sync(0xffffffffu, contrib, o);
            contrib = __shfl_sync(0xffffffffu, contrib, 0);
            run += contrib;
            base -= 32;
        }
        if (lane == 0) {
            sprefix = (u64)run;
            __threadfence();
            g_scanstate[b] = FLAG_PRE | (u64)(run + (long long)total);
        }
    }
    __syncthreads();
    int P = (int)sprefix;
    if (i < N) {
        g_off[i + 1] = incl + P;
        g_cur[i]     = incl - v + P;
        if (i == 0) g_off[0] = 0;
    }
}

// ---------------------------------------------------------------------------
// kD: place src ids into CSR slots (4 edges/thread). Also re-zeroes g_cnt,
// g_scanstate (consumed by kScan) and g_stat/g_k2b_ctr (for k2b later).
// ---------------------------------------------------------------------------
__global__ void kD_place(const int* __restrict__ ei, int E, int N)
{
    int t = blockIdx.x * blockDim.x + threadIdx.x;
    if (t < N)   g_cnt[t] = 0;
    if (t < 512) g_scanstate[t] = 0ULL;
    if (t < GG * 32) reinterpret_cast<float4*>(g_stat)[t] = make_float4(0.f, 0.f, 0.f, 0.f);
    if (t < GG) g_k2b_ctr[t] = 0;

    int base = t * 4;
#pragma unroll
    for (int u = 0; u < 4; u++) {
        int e = base + u;
        if (e < E) {
            int s = ei[e];
            int d = ei[E + e];
            int pos = atomicAdd(&g_cur[d], 1);
            g_srcidx[pos] = s;
        }
    }
}

// ---------------------------------------------------------------------------
// k2_fused: gather + tiled GEMM in one kernel.
//   agg[n] = sum_{s in nbr(n)} x[s];  A = [agg/deg | x] (128-k)
//   h = A @ [Wl;Wr]^T + bl
// Block: 128 nodes x 64 outputs, 256 threads.
//   Gather: 2 threads/node, 8 float4-channels each, CSR loop (MLP 8-16).
//   MMA: thread = 8 nodes x 4 outputs, 32 fp32 acc.
// Smem: sA k-major [128][128] (64KB) + sW [128][68] (34KB) = 100,352 B.
// ---------------------------------------------------------------------------
#define K2_TILE 128
#define SW_STRIDE 68
#define K2_SMEM_BYTES (128 * 128 * 4 + 128 * SW_STRIDE * 4)

__global__ __launch_bounds__(256) void k2_fused(
    const float* __restrict__ x,
    const float* __restrict__ Wl, const float* __restrict__ bl,
    const float* __restrict__ Wr, int N)
{
    extern __shared__ float smem[];
    float* sA = smem;                 // [k 0..127][node 0..127]
    float* sW = smem + 128 * 128;     // [k 0..127][j 0..63], row stride 68

    int tid = threadIdx.x;
    int n0 = blockIdx.x * K2_TILE;

    // --- weights: sW[k][j] = Wl[j][k]; sW[64+k][j] = Wr[j][k]
    for (int idx = tid; idx < 4096; idx += 256) {
        int j = idx >> 6, k = idx & 63;
        sW[k * SW_STRIDE + j] = __ldg(Wl + j * 64 + k);
        sW[(64 + k) * SW_STRIDE + j] = __ldg(Wr + j * 64 + k);
    }

    // --- gather + A-tile fill. 2 threads per node, 8 float4 channels each.
    {
        int nl = tid >> 1;        // 0..127
        int half = tid & 1;       // channel block: c4 in [half*8, half*8+8)
        int n = n0 + nl;
        if (n >= N) n = N - 1;    // clamp (results unused for OOB nodes)
        int off = g_off[n], end = g_off[n + 1];
        float inv = 1.0f / fmaxf((float)(end - off), 1.0f);

        const float4* x4 = reinterpret_cast<const float4*>(x);
        float4 acc[8];
#pragma unroll
        for (int i = 0; i < 8; i++) acc[i] = make_float4(0.f, 0.f, 0.f, 0.f);

        int k = off;
        for (; k + 1 < end; k += 2) {
            const float4* p0 = x4 + (size_t)g_srcidx[k] * 16 + half * 8;
            const float4* p1 = x4 + (size_t)g_srcidx[k + 1] * 16 + half * 8;
#pragma unroll
            for (int i = 0; i < 8; i++) {
                float4 v0 = __ldg(p0 + i);
                float4 v1 = __ldg(p1 + i);
                acc[i].x += v0.x + v1.x; acc[i].y += v0.y + v1.y;
                acc[i].z += v0.z + v1.z; acc[i].w += v0.w + v1.w;
            }
        }
        if (k < end) {
            const float4* p0 = x4 + (size_t)g_srcidx[k] * 16 + half * 8;
#pragma unroll
            for (int i = 0; i < 8; i++) {
                float4 v0 = __ldg(p0 + i);
                acc[i].x += v0.x; acc[i].y += v0.y;
                acc[i].z += v0.z; acc[i].w += v0.w;
            }
        }

        const float4* xo = x4 + (size_t)n * 16 + half * 8;
#pragma unroll
        for (int i = 0; i < 8; i++) {
            int kb = (half * 8 + i) * 4;
            float4 a = acc[i];
            sA[(kb + 0) * 128 + nl] = a.x * inv;
            sA[(kb + 1) * 128 + nl] = a.y * inv;
            sA[(kb + 2) * 128 + nl] = a.z * inv;
            sA[(kb + 3) * 128 + nl] = a.w * inv;
            float4 xv = __ldg(xo + i);
            sA[(64 + kb + 0) * 128 + nl] = xv.x;
            sA[(64 + kb + 1) * 128 + nl] = xv.y;
            sA[(64 + kb + 2) * 128 + nl] = xv.z;
            sA[(64 + kb + 3) * 128 + nl] = xv.w;
        }
    }
    __syncthreads();

    // --- MMA: thread = 8 nodes x 4 outputs
    int tx = tid & 15;   // output quad: j = tx*4..tx*4+3
    int ty = tid >> 4;   // node group: nl = ty*8..ty*8+7

    float acc[8][4];
    {
        float4 blv = __ldg(reinterpret_cast<const float4*>(bl) + tx);
#pragma unroll
        for (int i = 0; i < 8; i++) {
            acc[i][0] = blv.x; acc[i][1] = blv.y; acc[i][2] = blv.z; acc[i][3] = blv.w;
        }
    }

#pragma unroll 4
    for (int k = 0; k < 128; k++) {
        float4 w  = *reinterpret_cast<const float4*>(&sW[k * SW_STRIDE + tx * 4]);
        float4 a0 = *reinterpret_cast<const float4*>(&sA[k * 128 + ty * 8]);
        float4 a1 = *reinterpret_cast<const float4*>(&sA[k * 128 + ty * 8 + 4]);
        float av[8] = { a0.x, a0.y, a0.z, a0.w, a1.x, a1.y, a1.z, a1.w };
#pragma unroll
        for (int i = 0; i < 8; i++) {
            acc[i][0] = fmaf(av[i], w.x, acc[i][0]);
            acc[i][1] = fmaf(av[i], w.y, acc[i][1]);
            acc[i][2] = fmaf(av[i], w.z, acc[i][2]);
            acc[i][3] = fmaf(av[i], w.w, acc[i][3]);
        }
    }

    float4* h4 = reinterpret_cast<float4*>(g_h);
#pragma unroll
    for (int i = 0; i < 8; i++) {
        int n = n0 + ty * 8 + i;
        if (n < N)
            h4[(size_t)n * 16 + tx] = make_float4(acc[i][0], acc[i][1], acc[i][2], acc[i][3]);
    }
}

// ---------------------------------------------------------------------------
// k2b: per-graph stats, 8 slices/graph (grid=2048). Partial reduce into
// g_stat via red.add.v4; last-arriving block per graph finalizes mean/rstd.
// ---------------------------------------------------------------------------
__global__ __launch_bounds__(256) void k2b_part(
    const int* __restrict__ batch, const float* __restrict__ gn_alpha, int N)
{
    int g     = blockIdx.x >> 3;
    int c4 = threadIdx.x & 15;
    int r  = threadIdx.x >> 4;
    int slice = blockIdx.x & 7;

    int lo = 0, hi = N;
    while (lo < hi) { int mid = (lo + hi) >> 1; if (batch[mid] < g) lo = mid + 1; else hi = mid; }
    int start = lo;
    lo = start; hi = N;
    while (lo < hi) { int mid = (lo + hi) >> 1; if (batch[mid] < g + 1) lo = mid + 1; else hi = mid; }
    int end = lo;

    const float4* h4 = reinterpret_cast<const float4*>(g_h);
    float4 s0 = make_float4(0.f, 0.f, 0.f, 0.f), q0 = s0;

    for (int i = start + slice * 16 + r; i < end; i += 128) {
        float4 a = h4[(size_t)i * 16 + c4];
        s0.x += a.x; s0.y += a.y; s0.z += a.z; s0.w += a.w;
        q0.x = fmaf(a.x, a.x, q0.x); q0.y = fmaf(a.y, a.y, q0.y);
        q0.z = fmaf(a.z, a.z, q0.z); q0.w = fmaf(a.w, a.w, q0.w);
    }

    __shared__ __align__(16) float4 sS[16][16];
    __shared__ __align__(16) float4 sQ[16][16];
    sS[r][c4] = s0;
    sQ[r][c4] = q0;
    __syncthreads();
    for (int off = 8; off > 0; off >>= 1) {
        if (r < off) {
            float4 a = sS[r][c4], b = sS[r + off][c4];
            sS[r][c4] = make_float4(a.x + b.x, a.y + b.y, a.z + b.z, a.w + b.w);
            float4 c = sQ[r][c4], d = sQ[r + off][c4];
            sQ[r][c4] = make_float4(c.x + d.x, c.y + d.y, c.z + d.z, c.w + d.w);
        }
        __syncthreads();
    }
    if (r == 0) {
        red_add_v4(&g_stat[g * 128 + c4 * 4], sS[0][c4]);
        red_add_v4(&g_stat[g * 128 + 64 + c4 * 4], sQ[0][c4]);
        __threadfence();
    }
    __syncthreads();
    __shared__ int slast;
    if (threadIdx.x == 0) slast = (atomicAdd(&g_k2b_ctr[g], 1) == 7) ? 1 : 0;
    __syncthreads();
    if (slast && threadIdx.x < 64) {
        __threadfence();
        int c = threadIdx.x;
        float cnt = fmaxf((float)(end - start), 1.0f);
        float rinv = 1.0f / cnt;
        float sum = g_stat[g * 128 + c];
        float sq  = g_stat[g * 128 + 64 + c];
        float mu = sum * rinv;
        float al = gn_alpha[c];
        float fac = 2.0f * al - al * al;
        float var = fmaxf(sq * rinv - fac * mu * mu, 0.0f);
        g_mean[g * 64 + c] = mu;
        g_rstd[g * 64 + c] = rsqrtf(var + EPS);
    }
}

// ---------------------------------------------------------------------------
// K3: finalize with fused channel attention (16-lane shfl reduction).
// ---------------------------------------------------------------------------
__device__ __forceinline__ float f4get(const float4& v, int u)
{
    switch (u) { case 0: return v.x; case 1: return v.y; case 2: return v.z; default: return v.w; }
}

__global__ __launch_bounds__(256) void k3_finalize(
    const float* __restrict__ x, const int* __restrict__ batch,
    const float* __restrict__ gnw, const float* __restrict__ gnb,
    const float* __restrict__ gna,
    const float* __restrict__ a1w, const float* __restrict__ a1b,
    const float* __restrict__ a2w, const float* __restrict__ a2b,
    float* __restrict__ out, int N)
{
    int i = blockIdx.x * blockDim.x + threadIdx.x;
    int n  = i >> 4;
    int c4 = i & 15;
    int g  = batch[n];

    float4 xv = reinterpret_cast<const float4*>(x)[(size_t)n * 16 + c4];

    float t[8];
#pragma unroll
    for (int r = 0; r < 8; r++) {
        float4 a1v = __ldg(reinterpret_cast<const float4*>(a1w) + r * 16 + c4);
        t[r] = xv.x * a1v.x + xv.y * a1v.y + xv.z * a1v.z + xv.w * a1v.w;
    }
#pragma unroll
    for (int m = 1; m < 16; m <<= 1) {
#pragma unroll
        for (int r = 0; r < 8; r++)
            t[r] += __shfl_xor_sync(0xffffffffu, t[r], m);
    }
#pragma unroll
    for (int r = 0; r < 8; r++) t[r] = fmaxf(t[r] + __ldg(a1b + r), 0.0f);

    float4 hv = reinterpret_cast<const float4*>(g_h)[(size_t)n * 16 + c4];
    float4 mu = reinterpret_cast<const float4*>(g_mean)[g * 16 + c4];
    float4 rs = reinterpret_cast<const float4*>(g_rstd)[g * 16 + c4];
    float4 al = __ldg(reinterpret_cast<const float4*>(gna) + c4);
    float4 w4 = __ldg(reinterpret_cast<const float4*>(gnw) + c4);
    float4 b4 = __ldg(reinterpret_cast<const float4*>(gnb) + c4);
    float4 b2 = __ldg(reinterpret_cast<const float4*>(a2b) + c4);

    float res[4];
#pragma unroll
    for (int u = 0; u < 4; u++) {
        int j = c4 * 4 + u;
        float4 wa = __ldg(reinterpret_cast<const float4*>(a2w) + j * 2);
        float4 wb = __ldg(reinterpret_cast<const float4*>(a2w) + j * 2 + 1);
        float z = wa.x * t[0] + wa.y * t[1] + wa.z * t[2] + wa.w * t[3]
                + wb.x * t[4] + wb.y * t[5] + wb.z * t[6] + wb.w * t[7]
                + f4get(b2, u);
        float gate = 1.0f / (1.0f + __expf(-z));
        float y = f4get(w4, u) * (f4get(hv, u) - f4get(mu, u) * f4get(al, u)) * f4get(rs, u)
                + f4get(b4, u);
        res[u] = fmaxf(y + gate * f4get(xv, u), 0.0f);
    }
    reinterpret_cast<float4*>(out)[(size_t)n * 16 + c4] =
        make_float4(res[0], res[1], res[2], res[3]);
}

// ---------------------------------------------------------------------------
// launch (6 kernels; 4th = k2_fused, which the profiler captures)
// ---------------------------------------------------------------------------
extern "C" void kernel_launch(void* const* d_in, const int* in_sizes, int n_in,
                              void* d_out, int out_size)
{
    const float* x     = (const float*)d_in[0];
    const int*   ei    = (const int*)d_in[1];     // int32 (JAX x64 disabled)
    const int*   batch = (const int*)d_in[2];     // int32
    const float* Wl    = (const float*)d_in[3];
    const float* bl    = (const float*)d_in[4];
    const float* Wr    = (const float*)d_in[5];
    const float* gnw   = (const float*)d_in[6];
    const float* gnb   = (const float*)d_in[7];
    const float* gna   = (const float*)d_in[8];
    const float* a1w   = (const float*)d_in[9];
    const float* a1b   = (const float*)d_in[10];
    const float* a2w   = (const float*)d_in[11];
    const float* a2b   = (const float*)d_in[12];
    float*       out   = (float*)d_out;

    int N = in_sizes[0] / CC;          // 100000
    int E = in_sizes[1] / 2;           // 1200000
    int nb = (N + 255) / 256;          // 391 scan blocks
    int ne4 = ((E + 3) / 4 + 255) / 256;  // edge kernels, 4 edges/thread

    cudaFuncSetAttribute(k2_fused, cudaFuncAttributeMaxDynamicSharedMemorySize,
                         K2_SMEM_BYTES);

    kB_hist<<<ne4, 256>>>(ei, E);
    kScan<<<nb, 256>>>(N);
    kD_place<<<ne4, 256>>>(ei, E, N);
    k2_fused<<<(N + K2_TILE - 1) / K2_TILE, 256, K2_SMEM_BYTES>>>(x, Wl, bl, Wr, N);
    k2b_part<<<GG * 8, 256>>>(batch, gna, N);
    k3_finalize<<<(N * 16 + 255) / 256, 256>>>(x, batch, gnw, gnb, gna,
                                               a1w, a1b, a2w, a2b, out, N);
}

// round 15
// speedup vs baseline: 1.3394x; 1.3394x over previous
#include <cuda_runtime.h>
#include <cuda_bf16.h>
#include <stdint.h>

// Problem constants (fixed by the dataset)
#define NN 100000
#define CC 64
#define EE 1200000
#define GG 256
#define EPS 1e-5f

typedef unsigned long long u64;

#define FLAG_AGG (1ULL << 62)
#define FLAG_PRE (2ULL << 62)
#define VALMASK  ((1ULL << 62) - 1ULL)

// ---------------------------------------------------------------------------
// Scratch (device globals; loader zero-initialized; each call re-zeroes what
// it dirties AFTER last use so the graph stays deterministic).
// ---------------------------------------------------------------------------
__device__ __align__(16) float g_agg[NN * CC];    // neighbor-sum (gather output)
__device__ __align__(16) float g_deg[NN];         // in-degree (float)
__device__ __align__(16) float g_h[NN * CC];      // SAGE output
__device__ __align__(16) float g_mean[GG * CC];   // per-graph mean
__device__ __align__(16) float g_rstd[GG * CC];   // per-graph rsqrt(var+eps)
__device__ __align__(16) float g_stat[GG * 128];  // per-graph partial sum[64]|sq[64]

__device__ __align__(16) int g_cnt[NN];           // in-degree counts (zeroed by kD)
__device__ __align__(16) int g_off[NN + 1];       // CSR offsets
__device__ __align__(16) int g_cur[NN];           // placement cursors
__device__ __align__(16) int g_srcidx[EE];        // CSR: src node per slot
__device__ int g_k2b_ctr[GG];                     // last-block counters (zeroed by kE)
__device__ volatile u64 g_scanstate[512];         // lookback state (zeroed by kD)

__device__ __forceinline__ void red_add_v4(float* addr, float4 v)
{
    asm volatile("red.global.add.v4.f32 [%0], {%1, %2, %3, %4};"
                 :: "l"(addr), "f"(v.x), "f"(v.y), "f"(v.z), "f"(v.w)
                 : "memory");
}

// ---------------------------------------------------------------------------
// kB: histogram of in-degree. 4 edges/thread.
// ---------------------------------------------------------------------------
__global__ void kB_hist(const int* __restrict__ ei, int E)
{
    int base = (blockIdx.x * blockDim.x + threadIdx.x) * 4;
#pragma unroll
    for (int u = 0; u < 4; u++) {
        int e = base + u;
        if (e < E) atomicAdd(&g_cnt[ei[E + e]], 1);
    }
}

// ---------------------------------------------------------------------------
// kScan: single-pass exclusive scan of g_cnt -> g_off[N+1], g_cur
// ---------------------------------------------------------------------------
__global__ __launch_bounds__(256) void kScan(int N)
{
    int b = blockIdx.x;
    int i = b * 256 + threadIdx.x;
    int lane = threadIdx.x & 31, w = threadIdx.x >> 5;

    int v = (i < N) ? g_cnt[i] : 0;
    int s = v;
#pragma unroll
    for (int o = 1; o < 32; o <<= 1) {
        int t = __shfl_up_sync(0xffffffffu, s, o);
        if (lane >= o) s += t;
    }
    __shared__ int wsum[8], woff[8], sbtot;
    __shared__ u64 sprefix;
    if (lane == 31) wsum[w] = s;
    __syncthreads();
    if (threadIdx.x == 0) {
        int acc = 0;
#pragma unroll
        for (int k = 0; k < 8; k++) { woff[k] = acc; acc += wsum[k]; }
        sbtot = acc;
        __threadfence();
        g_scanstate[b] = (b == 0 ? FLAG_PRE : FLAG_AGG) | (u64)acc;
        if (b == 0) sprefix = 0ULL;
    }
    __syncthreads();
    int incl = s + woff[w];
    int total = sbtot;

    if (b > 0 && w == 0) {
        long long run = 0;
        int base = b - 1;
        bool done = false;
        while (!done) {
            int idx = base - lane;
            u64 st = FLAG_PRE;
            if (idx >= 0) {
                do { st = g_scanstate[idx]; } while ((st >> 62) == 0ULL);
            }
            unsigned pre = __ballot_sync(0xffffffffu, (st >> 62) == 2ULL);
            long long val = (long long)(st & VALMASK);
            long long contrib;
            if (pre) {
                int firstpre = __ffs(pre) - 1;
                contrib = (lane <= firstpre) ? val : 0;
                done = true;
            } else {
                contrib = val;
            }
#pragma unroll
            for (int o = 16; o > 0; o >>= 1)
                contrib += __shfl_down_sync(0xffffffffu, contrib, o);
            contrib = __shfl_sync(0xffffffffu, contrib, 0);
            run += contrib;
            base -= 32;
        }
        if (lane == 0) {
            sprefix = (u64)run;
            __threadfence();
            g_scanstate[b] = FLAG_PRE | (u64)(run + (long long)total);
        }
    }
    __syncthreads();
    int P = (int)sprefix;
    if (i < N) {
        g_off[i + 1] = incl + P;
        g_cur[i]     = incl - v + P;
        if (i == 0) g_off[0] = 0;
    }
}

// ---------------------------------------------------------------------------
// kD: place src ids into CSR slots (4 edges/thread). Re-zeroes g_cnt and
// g_scanstate (fully consumed by kScan).
// ---------------------------------------------------------------------------
__global__ void kD_place(const int* __restrict__ ei, int E, int N)
{
    int t = blockIdx.x * blockDim.x + threadIdx.x;
    if (t < N)   g_cnt[t] = 0;
    if (t < 512) g_scanstate[t] = 0ULL;

    int base = t * 4;
#pragma unroll
    for (int u = 0; u < 4; u++) {
        int e = base + u;
        if (e < E) {
            int s = ei[e];
            int d = ei[E + e];
            int pos = atomicAdd(&g_cur[d], 1);
            g_srcidx[pos] = s;
        }
    }
}

// ---------------------------------------------------------------------------
// kE: gather-aggregate. 16 threads per node; each owns one float4 channel
// group; neighbor loop unrolled x4 (up to 16 loads in flight per thread).
// Also zeroes g_stat / g_k2b_ctr for the k2b stage.
// ---------------------------------------------------------------------------
__global__ __launch_bounds__(256) void kE_gather(const float* __restrict__ x, int N)
{
    int gidx = blockIdx.x * 256 + threadIdx.x;
    if (gidx < GG * 32) reinterpret_cast<float4*>(g_stat)[gidx] = make_float4(0.f, 0.f, 0.f, 0.f);
    if (gidx < GG) g_k2b_ctr[gidx] = 0;

    int n  = gidx >> 4;
    int c4 = gidx & 15;
    if (n >= N) return;
    int off = g_off[n], end = g_off[n + 1];

    const float4* x4 = reinterpret_cast<const float4*>(x);
    float4 a0 = make_float4(0.f, 0.f, 0.f, 0.f);
    float4 a1 = a0, a2 = a0, a3 = a0;

    int k = off;
    for (; k + 3 < end; k += 4) {
        float4 v0 = __ldg(x4 + (size_t)g_srcidx[k] * 16 + c4);
        float4 v1 = __ldg(x4 + (size_t)g_srcidx[k + 1] * 16 + c4);
        float4 v2 = __ldg(x4 + (size_t)g_srcidx[k + 2] * 16 + c4);
        float4 v3 = __ldg(x4 + (size_t)g_srcidx[k + 3] * 16 + c4);
        a0.x += v0.x; a0.y += v0.y; a0.z += v0.z; a0.w += v0.w;
        a1.x += v1.x; a1.y += v1.y; a1.z += v1.z; a1.w += v1.w;
        a2.x += v2.x; a2.y += v2.y; a2.z += v2.z; a2.w += v2.w;
        a3.x += v3.x; a3.y += v3.y; a3.z += v3.z; a3.w += v3.w;
    }
    for (; k < end; k++) {
        float4 v0 = __ldg(x4 + (size_t)g_srcidx[k] * 16 + c4);
        a0.x += v0.x; a0.y += v0.y; a0.z += v0.z; a0.w += v0.w;
    }
    a0.x += a1.x + a2.x + a3.x;
    a0.y += a1.y + a2.y + a3.y;
    a0.z += a1.z + a2.z + a3.z;
    a0.w += a1.w + a2.w + a3.w;

    reinterpret_cast<float4*>(g_agg)[(size_t)n * 16 + c4] = a0;
    if (c4 == 0) g_deg[n] = (float)(end - off);
}

// ---------------------------------------------------------------------------
// K2: tiled register-blocked GEMM (fp32), 64-node tile for 3 blocks/SM:
//   h = [agg/deg | x] (N x 128) @ [Wl ; Wr] + bl
// Block: 64 nodes x 64 outputs, 256 threads; thread = 4 nodes x 4 outputs.
// Smem: sA k-major [128][64] (32KB) + sW [128][68] (34KB) = 67,584 B.
// ---------------------------------------------------------------------------
#define K2_TILE 64
#define SW_STRIDE 68
#define K2_SMEM_BYTES (128 * 64 * 4 + 128 * SW_STRIDE * 4)

__global__ __launch_bounds__(256) void k2_gemm(
    const float* __restrict__ x,
    const float* __restrict__ Wl, const float* __restrict__ bl,
    const float* __restrict__ Wr, int N)
{
    extern __shared__ float smem[];
    float* sA = smem;                 // [k 0..127][node 0..63]
    float* sW = smem + 128 * 64;      // [k 0..127][j 0..63], row stride 68

    int tid = threadIdx.x;
    int n0 = blockIdx.x * K2_TILE;

    // --- weights: sW[k][j] = Wl[j][k]; sW[64+k][j] = Wr[j][k]
    for (int idx = tid; idx < 4096; idx += 256) {
        int j = idx >> 6, k = idx & 63;
        sW[k * SW_STRIDE + j] = __ldg(Wl + j * 64 + k);
        sW[(64 + k) * SW_STRIDE + j] = __ldg(Wr + j * 64 + k);
    }

    // --- A-tile fill: 4 threads/node, each handles 4 c4-groups of agg AND x
    {
        int nl = tid >> 2;        // 0..63
        int q  = tid & 3;         // 0..3 -> c4 in [q*4, q*4+4)
        int n = n0 + nl; if (n >= N) n = N - 1;
        float inv = 1.0f / fmaxf(g_deg[n], 1.0f);
        const float4* ag4 = reinterpret_cast<const float4*>(g_agg) + (size_t)n * 16;
        const float4* xx4 = reinterpret_cast<const float4*>(x) + (size_t)n * 16;
#pragma unroll
        for (int i = 0; i < 4; i++) {
            int c4 = q * 4 + i;
            int kb = c4 * 4;
            float4 a = ag4[c4];
            sA[(kb + 0) * 64 + nl] = a.x * inv;
            sA[(kb + 1) * 64 + nl] = a.y * inv;
            sA[(kb + 2) * 64 + nl] = a.z * inv;
            sA[(kb + 3) * 64 + nl] = a.w * inv;
            float4 xv = __ldg(xx4 + c4);
            sA[(64 + kb + 0) * 64 + nl] = xv.x;
            sA[(64 + kb + 1) * 64 + nl] = xv.y;
            sA[(64 + kb + 2) * 64 + nl] = xv.z;
            sA[(64 + kb + 3) * 64 + nl] = xv.w;
        }
    }
    __syncthreads();

    // --- MMA: thread = 4 nodes x 4 outputs
    int tx = tid & 15;   // output quad: j = tx*4..tx*4+3
    int ty = tid >> 4;   // node group: nl = ty*4..ty*4+3

    float acc[4][4];
    {
        float4 blv = __ldg(reinterpret_cast<const float4*>(bl) + tx);
#pragma unroll
        for (int i = 0; i < 4; i++) {
            acc[i][0] = blv.x; acc[i][1] = blv.y; acc[i][2] = blv.z; acc[i][3] = blv.w;
        }
    }

#pragma unroll 4
    for (int k = 0; k < 128; k++) {
        float4 w  = *reinterpret_cast<const float4*>(&sW[k * SW_STRIDE + tx * 4]);
        float4 a0 = *reinterpret_cast<const float4*>(&sA[k * 64 + ty * 4]);
        float av[4] = { a0.x, a0.y, a0.z, a0.w };
#pragma unroll
        for (int i = 0; i < 4; i++) {
            acc[i][0] = fmaf(av[i], w.x, acc[i][0]);
            acc[i][1] = fmaf(av[i], w.y, acc[i][1]);
            acc[i][2] = fmaf(av[i], w.z, acc[i][2]);
            acc[i][3] = fmaf(av[i], w.w, acc[i][3]);
        }
    }

    float4* h4 = reinterpret_cast<float4*>(g_h);
#pragma unroll
    for (int i = 0; i < 4; i++) {
        int n = n0 + ty * 4 + i;
        if (n < N)
            h4[(size_t)n * 16 + tx] = make_float4(acc[i][0], acc[i][1], acc[i][2], acc[i][3]);
    }
}

// ---------------------------------------------------------------------------
// k2b: per-graph stats, 8 slices/graph (grid=2048). Partial reduce into
// g_stat via red.add.v4; last-arriving block per graph finalizes mean/rstd.
// ---------------------------------------------------------------------------
__global__ __launch_bounds__(256) void k2b_part(
    const int* __restrict__ batch, const float* __restrict__ gn_alpha, int N)
{
    int g     = blockIdx.x >> 3;
    int c4 = threadIdx.x & 15;
    int r  = threadIdx.x >> 4;
    int slice = blockIdx.x & 7;

    int lo = 0, hi = N;
    while (lo < hi) { int mid = (lo + hi) >> 1; if (batch[mid] < g) lo = mid + 1; else hi = mid; }
    int start = lo;
    lo = start; hi = N;
    while (lo < hi) { int mid = (lo + hi) >> 1; if (batch[mid] < g + 1) lo = mid + 1; else hi = mid; }
    int end = lo;

    const float4* h4 = reinterpret_cast<const float4*>(g_h);
    float4 s0 = make_float4(0.f, 0.f, 0.f, 0.f), q0 = s0;

    for (int i = start + slice * 16 + r; i < end; i += 128) {
        float4 a = h4[(size_t)i * 16 + c4];
        s0.x += a.x; s0.y += a.y; s0.z += a.z; s0.w += a.w;
        q0.x = fmaf(a.x, a.x, q0.x); q0.y = fmaf(a.y, a.y, q0.y);
        q0.z = fmaf(a.z, a.z, q0.z); q0.w = fmaf(a.w, a.w, q0.w);
    }

    __shared__ __align__(16) float4 sS[16][16];
    __shared__ __align__(16) float4 sQ[16][16];
    sS[r][c4] = s0;
    sQ[r][c4] = q0;
    __syncthreads();
    for (int off = 8; off > 0; off >>= 1) {
        if (r < off) {
            float4 a = sS[r][c4], b = sS[r + off][c4];
            sS[r][c4] = make_float4(a.x + b.x, a.y + b.y, a.z + b.z, a.w + b.w);
            float4 c = sQ[r][c4], d = sQ[r + off][c4];
            sQ[r][c4] = make_float4(c.x + d.x, c.y + d.y, c.z + d.z, c.w + d.w);
        }
        __syncthreads();
    }
    if (r == 0) {
        red_add_v4(&g_stat[g * 128 + c4 * 4], sS[0][c4]);
        red_add_v4(&g_stat[g * 128 + 64 + c4 * 4], sQ[0][c4]);
        __threadfence();
    }
    __syncthreads();
    __shared__ int slast;
    if (threadIdx.x == 0) slast = (atomicAdd(&g_k2b_ctr[g], 1) == 7) ? 1 : 0;
    __syncthreads();
    if (slast && threadIdx.x < 64) {
        __threadfence();
        int c = threadIdx.x;
        float cnt = fmaxf((float)(end - start), 1.0f);
        float rinv = 1.0f / cnt;
        float sum = g_stat[g * 128 + c];
        float sq  = g_stat[g * 128 + 64 + c];
        float mu = sum * rinv;
        float al = gn_alpha[c];
        float fac = 2.0f * al - al * al;
        float var = fmaxf(sq * rinv - fac * mu * mu, 0.0f);
        g_mean[g * 64 + c] = mu;
        g_rstd[g * 64 + c] = rsqrtf(var + EPS);
    }
}

// ---------------------------------------------------------------------------
// K3: finalize with fused channel attention (16-lane shfl reduction).
// ---------------------------------------------------------------------------
__device__ __forceinline__ float f4get(const float4& v, int u)
{
    switch (u) { case 0: return v.x; case 1: return v.y; case 2: return v.z; default: return v.w; }
}

__global__ __launch_bounds__(256) void k3_finalize(
    const float* __restrict__ x, const int* __restrict__ batch,
    const float* __restrict__ gnw, const float* __restrict__ gnb,
    const float* __restrict__ gna,
    const float* __restrict__ a1w, const float* __restrict__ a1b,
    const float* __restrict__ a2w, const float* __restrict__ a2b,
    float* __restrict__ out, int N)
{
    int i = blockIdx.x * blockDim.x + threadIdx.x;
    int n  = i >> 4;
    int c4 = i & 15;
    int g  = batch[n];

    float4 xv = reinterpret_cast<const float4*>(x)[(size_t)n * 16 + c4];

    float t[8];
#pragma unroll
    for (int r = 0; r < 8; r++) {
        float4 a1v = __ldg(reinterpret_cast<const float4*>(a1w) + r * 16 + c4);
        t[r] = xv.x * a1v.x + xv.y * a1v.y + xv.z * a1v.z + xv.w * a1v.w;
    }
#pragma unroll
    for (int m = 1; m < 16; m <<= 1) {
#pragma unroll
        for (int r = 0; r < 8; r++)
            t[r] += __shfl_xor_sync(0xffffffffu, t[r], m);
    }
#pragma unroll
    for (int r = 0; r < 8; r++) t[r] = fmaxf(t[r] + __ldg(a1b + r), 0.0f);

    float4 hv = reinterpret_cast<const float4*>(g_h)[(size_t)n * 16 + c4];
    float4 mu = reinterpret_cast<const float4*>(g_mean)[g * 16 + c4];
    float4 rs = reinterpret_cast<const float4*>(g_rstd)[g * 16 + c4];
    float4 al = __ldg(reinterpret_cast<const float4*>(gna) + c4);
    float4 w4 = __ldg(reinterpret_cast<const float4*>(gnw) + c4);
    float4 b4 = __ldg(reinterpret_cast<const float4*>(gnb) + c4);
    float4 b2 = __ldg(reinterpret_cast<const float4*>(a2b) + c4);

    float res[4];
#pragma unroll
    for (int u = 0; u < 4; u++) {
        int j = c4 * 4 + u;
        float4 wa = __ldg(reinterpret_cast<const float4*>(a2w) + j * 2);
        float4 wb = __ldg(reinterpret_cast<const float4*>(a2w) + j * 2 + 1);
        float z = wa.x * t[0] + wa.y * t[1] + wa.z * t[2] + wa.w * t[3]
                + wb.x * t[4] + wb.y * t[5] + wb.z * t[6] + wb.w * t[7]
                + f4get(b2, u);
        float gate = 1.0f / (1.0f + __expf(-z));
        float y = f4get(w4, u) * (f4get(hv, u) - f4get(mu, u) * f4get(al, u)) * f4get(rs, u)
                + f4get(b4, u);
        res[u] = fmaxf(y + gate * f4get(xv, u), 0.0f);
    }
    reinterpret_cast<float4*>(out)[(size_t)n * 16 + c4] =
        make_float4(res[0], res[1], res[2], res[3]);
}

// ---------------------------------------------------------------------------
// launch (7 kernels; 4th = kE_gather, profiler slot)
// ---------------------------------------------------------------------------
extern "C" void kernel_launch(void* const* d_in, const int* in_sizes, int n_in,
                              void* d_out, int out_size)
{
    const float* x     = (const float*)d_in[0];
    const int*   ei    = (const int*)d_in[1];     // int32 (JAX x64 disabled)
    const int*   batch = (const int*)d_in[2];     // int32
    const float* Wl    = (const float*)d_in[3];
    const float* bl    = (const float*)d_in[4];
    const float* Wr    = (const float*)d_in[5];
    const float* gnw   = (const float*)d_in[6];
    const float* gnb   = (const float*)d_in[7];
    const float* gna   = (const float*)d_in[8];
    const float* a1w   = (const float*)d_in[9];
    const float* a1b   = (const float*)d_in[10];
    const float* a2w   = (const float*)d_in[11];
    const float* a2b   = (const float*)d_in[12];
    float*       out   = (float*)d_out;

    int N = in_sizes[0] / CC;          // 100000
    int E = in_sizes[1] / 2;           // 1200000
    int nb = (N + 255) / 256;          // 391 scan blocks
    int ne4 = ((E + 3) / 4 + 255) / 256;  // edge kernels, 4 edges/thread

    cudaFuncSetAttribute(k2_gemm, cudaFuncAttributeMaxDynamicSharedMemorySize,
                         K2_SMEM_BYTES);

    kB_hist<<<ne4, 256>>>(ei, E);
    kScan<<<nb, 256>>>(N);
    kD_place<<<ne4, 256>>>(ei, E, N);
    kE_gather<<<(N * 16 + 255) / 256, 256>>>(x, N);
    k2_gemm<<<(N + K2_TILE - 1) / K2_TILE, 256, K2_SMEM_BYTES>>>(x, Wl, bl, Wr, N);
    k2b_part<<<GG * 8, 256>>>(batch, gna, N);
    k3_finalize<<<(N * 16 + 255) / 256, 256>>>(x, batch, gnw, gnb, gna,
                                               a1w, a1b, a2w, a2b, out, N);
}

// round 16
// speedup vs baseline: 1.4048x; 1.0489x over previous
#include <cuda_runtime.h>
#include <cuda_bf16.h>
#include <stdint.h>

// Problem constants (fixed by the dataset)
#define NN 100000
#define CC 64
#define EE 1200000
#define GG 256
#define EPS 1e-5f

typedef unsigned long long u64;

#define FLAG_AGG (1ULL << 62)
#define FLAG_PRE (2ULL << 62)
#define VALMASK  ((1ULL << 62) - 1ULL)

// ---------------------------------------------------------------------------
// Scratch (device globals; loader zero-initialized; each call re-zeroes what
// it dirties AFTER last use so the graph stays deterministic).
// ---------------------------------------------------------------------------
__device__ __align__(16) float g_agg[NN * CC];    // neighbor-sum (gather output)
__device__ __align__(16) float g_deg[NN];         // in-degree (float)
__device__ __align__(16) float g_h[NN * CC];      // SAGE output
__device__ __align__(16) float g_mean[GG * CC];   // per-graph mean
__device__ __align__(16) float g_rstd[GG * CC];   // per-graph rsqrt(var+eps)
__device__ __align__(16) float g_stat[GG * 128];  // per-graph partial sum[64]|sq[64]

__device__ __align__(16) int g_cnt[NN];           // in-degree counts (zeroed by kD)
__device__ __align__(16) int g_off[NN + 1];       // CSR offsets
__device__ __align__(16) int g_cur[NN];           // placement cursors
__device__ __align__(16) int g_srcidx[EE];        // CSR: src node per slot
__device__ int g_k2b_ctr[GG];                     // last-block counters (zeroed by kE)
__device__ volatile u64 g_scanstate[512];         // lookback state (zeroed by kD)
__device__ int g_bar;                             // kHS grid barrier (zeroed by kD)

__device__ __forceinline__ void red_add_v4(float* addr, float4 v)
{
    asm volatile("red.global.add.v4.f32 [%0], {%1, %2, %3, %4};"
                 :: "l"(addr), "f"(v.x), "f"(v.y), "f"(v.z), "f"(v.w)
                 : "memory");
}

// ---------------------------------------------------------------------------
// kHS: fused histogram + exclusive scan.
// 391 blocks (ALL co-resident: 100K threads << chip capacity, so the
// atomic-counter grid barrier is deadlock-free).
// Phase A: grid-strided histogram of edge destinations.
// Barrier: counter arrive + spin.
// Phase B: decoupled-lookback exclusive scan -> g_off[N+1], g_cur.
// ---------------------------------------------------------------------------
__global__ __launch_bounds__(256) void kHS(const int* __restrict__ ei, int E, int N)
{
    int b = blockIdx.x;
    int tid = threadIdx.x;
    int nthr = gridDim.x * 256;

    // --- Phase A: histogram
    for (int e = b * 256 + tid; e < E; e += nthr)
        atomicAdd(&g_cnt[ei[E + e]], 1);
    __syncthreads();
    if (tid == 0) {
        __threadfence();
        atomicAdd(&g_bar, 1);
        while (atomicAdd(&g_bar, 0) < gridDim.x) { }
    }
    __syncthreads();
    __threadfence();

    // --- Phase B: scan (decoupled lookback)
    int i = b * 256 + tid;
    int lane = tid & 31, w = tid >> 5;

    int v = (i < N) ? g_cnt[i] : 0;
    int s = v;
#pragma unroll
    for (int o = 1; o < 32; o <<= 1) {
        int t = __shfl_up_sync(0xffffffffu, s, o);
        if (lane >= o) s += t;
    }
    __shared__ int wsum[8], woff[8], sbtot;
    __shared__ u64 sprefix;
    if (lane == 31) wsum[w] = s;
    __syncthreads();
    if (tid == 0) {
        int acc = 0;
#pragma unroll
        for (int k = 0; k < 8; k++) { woff[k] = acc; acc += wsum[k]; }
        sbtot = acc;
        __threadfence();
        g_scanstate[b] = (b == 0 ? FLAG_PRE : FLAG_AGG) | (u64)acc;
        if (b == 0) sprefix = 0ULL;
    }
    __syncthreads();
    int incl = s + woff[w];
    int total = sbtot;

    if (b > 0 && w == 0) {
        long long run = 0;
        int base = b - 1;
        bool done = false;
        while (!done) {
            int idx = base - lane;
            u64 st = FLAG_PRE;
            if (idx >= 0) {
                do { st = g_scanstate[idx]; } while ((st >> 62) == 0ULL);
            }
            unsigned pre = __ballot_sync(0xffffffffu, (st >> 62) == 2ULL);
            long long val = (long long)(st & VALMASK);
            long long contrib;
            if (pre) {
                int firstpre = __ffs(pre) - 1;
                contrib = (lane <= firstpre) ? val : 0;
                done = true;
            } else {
                contrib = val;
            }
#pragma unroll
            for (int o = 16; o > 0; o >>= 1)
                contrib += __shfl_down_sync(0xffffffffu, contrib, o);
            contrib = __shfl_sync(0xffffffffu, contrib, 0);
            run += contrib;
            base -= 32;
        }
        if (lane == 0) {
            sprefix = (u64)run;
            __threadfence();
            g_scanstate[b] = FLAG_PRE | (u64)(run + (long long)total);
        }
    }
    __syncthreads();
    int P = (int)sprefix;
    if (i < N) {
        g_off[i + 1] = incl + P;
        g_cur[i]     = incl - v + P;
        if (i == 0) g_off[0] = 0;
    }
}

// ---------------------------------------------------------------------------
// kD: place src ids into CSR slots (4 edges/thread). Re-zeroes g_cnt,
// g_scanstate and g_bar (fully consumed by kHS).
// ---------------------------------------------------------------------------
__global__ void kD_place(const int* __restrict__ ei, int E, int N)
{
    int t = blockIdx.x * blockDim.x + threadIdx.x;
    if (t < N)   g_cnt[t] = 0;
    if (t < 512) g_scanstate[t] = 0ULL;
    if (t == 0)  g_bar = 0;

    int base = t * 4;
#pragma unroll
    for (int u = 0; u < 4; u++) {
        int e = base + u;
        if (e < E) {
            int s = ei[e];
            int d = ei[E + e];
            int pos = atomicAdd(&g_cur[d], 1);
            g_srcidx[pos] = s;
        }
    }
}

// ---------------------------------------------------------------------------
// kE: gather-aggregate (R13-proven config: unroll 2, 32 regs, occ ~74%).
// 16 threads per node; each owns one float4 channel group.
// Also zeroes g_stat / g_k2b_ctr for the k2b stage.
// ---------------------------------------------------------------------------
__global__ __launch_bounds__(256) void kE_gather(const float* __restrict__ x, int N)
{
    int gidx = blockIdx.x * 256 + threadIdx.x;
    if (gidx < GG * 32) reinterpret_cast<float4*>(g_stat)[gidx] = make_float4(0.f, 0.f, 0.f, 0.f);
    if (gidx < GG) g_k2b_ctr[gidx] = 0;

    int n  = gidx >> 4;
    int c4 = gidx & 15;
    if (n >= N) return;
    int off = g_off[n], end = g_off[n + 1];

    const float4* x4 = reinterpret_cast<const float4*>(x);
    float4 a0 = make_float4(0.f, 0.f, 0.f, 0.f);
    float4 a1 = a0;

    int k = off;
    for (; k + 1 < end; k += 2) {
        int s0 = g_srcidx[k];
        int s1 = g_srcidx[k + 1];
        float4 v0 = __ldg(x4 + (size_t)s0 * 16 + c4);
        float4 v1 = __ldg(x4 + (size_t)s1 * 16 + c4);
        a0.x += v0.x; a0.y += v0.y; a0.z += v0.z; a0.w += v0.w;
        a1.x += v1.x; a1.y += v1.y; a1.z += v1.z; a1.w += v1.w;
    }
    if (k < end) {
        int s0 = g_srcidx[k];
        float4 v0 = __ldg(x4 + (size_t)s0 * 16 + c4);
        a0.x += v0.x; a0.y += v0.y; a0.z += v0.z; a0.w += v0.w;
    }
    a0.x += a1.x; a0.y += a1.y; a0.z += a1.z; a0.w += a1.w;

    reinterpret_cast<float4*>(g_agg)[(size_t)n * 16 + c4] = a0;
    if (c4 == 0) g_deg[n] = (float)(end - off);
}

// ---------------------------------------------------------------------------
// K2: tiled register-blocked GEMM (R13-proven 128-node tile):
//   h = [agg/deg | x] (N x 128) @ [Wl ; Wr] + bl
// Block: 128 nodes x 64 outputs, 256 threads; thread = 8 nodes x 4 outputs.
// Smem: sA k-major [128][128] (64KB) + sW [128][68] (34KB) = 100,352 B.
// ---------------------------------------------------------------------------
#define K2_TILE 128
#define SW_STRIDE 68
#define K2_SMEM_BYTES (128 * 128 * 4 + 128 * SW_STRIDE * 4)

__global__ __launch_bounds__(256) void k2_gemm(
    const float* __restrict__ x,
    const float* __restrict__ Wl, const float* __restrict__ bl,
    const float* __restrict__ Wr, int N)
{
    extern __shared__ float smem[];
    float* sA = smem;                 // [k 0..127][node 0..127]
    float* sW = smem + 128 * 128;     // [k 0..127][j 0..63], row stride 68

    int tid = threadIdx.x;
    int n0 = blockIdx.x * K2_TILE;

    for (int idx = tid; idx < 4096; idx += 256) {
        int j = idx >> 6, k = idx & 63;
        sW[k * SW_STRIDE + j] = __ldg(Wl + j * 64 + k);
        sW[(64 + k) * SW_STRIDE + j] = __ldg(Wr + j * 64 + k);
    }

    {
        int nl = tid & 127, half = tid >> 7;
        int n = n0 + nl; if (n >= N) n = N - 1;
        float inv = 1.0f / fmaxf(g_deg[n], 1.0f);
        const float4* ag4 = reinterpret_cast<const float4*>(g_agg) + (size_t)n * 16;
        const float4* xx4 = reinterpret_cast<const float4*>(x) + (size_t)n * 16;
#pragma unroll
        for (int i = 0; i < 8; i++) {
            int c4 = half * 8 + i;
            float4 a = ag4[c4];
            float4 xv = __ldg(xx4 + c4);
            int kb = c4 * 4;
            sA[(kb + 0) * 128 + nl] = a.x * inv;
            sA[(kb + 1) * 128 + nl] = a.y * inv;
            sA[(kb + 2) * 128 + nl] = a.z * inv;
            sA[(kb + 3) * 128 + nl] = a.w * inv;
            sA[(64 + kb + 0) * 128 + nl] = xv.x;
            sA[(64 + kb + 1) * 128 + nl] = xv.y;
            sA[(64 + kb + 2) * 128 + nl] = xv.z;
            sA[(64 + kb + 3) * 128 + nl] = xv.w;
        }
    }
    __syncthreads();

    int tx = tid & 15;   // output quad: j = tx*4..tx*4+3
    int ty = tid >> 4;   // node group: nl = ty*8..ty*8+7

    float acc[8][4];
    {
        float4 blv = __ldg(reinterpret_cast<const float4*>(bl) + tx);
#pragma unroll
        for (int i = 0; i < 8; i++) {
            acc[i][0] = blv.x; acc[i][1] = blv.y; acc[i][2] = blv.z; acc[i][3] = blv.w;
        }
    }

#pragma unroll 4
    for (int k = 0; k < 128; k++) {
        float4 w  = *reinterpret_cast<const float4*>(&sW[k * SW_STRIDE + tx * 4]);
        float4 a0 = *reinterpret_cast<const float4*>(&sA[k * 128 + ty * 8]);
        float4 a1 = *reinterpret_cast<const float4*>(&sA[k * 128 + ty * 8 + 4]);
        float av[8] = { a0.x, a0.y, a0.z, a0.w, a1.x, a1.y, a1.z, a1.w };
#pragma unroll
        for (int i = 0; i < 8; i++) {
            acc[i][0] = fmaf(av[i], w.x, acc[i][0]);
            acc[i][1] = fmaf(av[i], w.y, acc[i][1]);
            acc[i][2] = fmaf(av[i], w.z, acc[i][2]);
            acc[i][3] = fmaf(av[i], w.w, acc[i][3]);
        }
    }

    float4* h4 = reinterpret_cast<float4*>(g_h);
#pragma unroll
    for (int i = 0; i < 8; i++) {
        int n = n0 + ty * 8 + i;
        if (n < N)
            h4[(size_t)n * 16 + tx] = make_float4(acc[i][0], acc[i][1], acc[i][2], acc[i][3]);
    }
}

// ---------------------------------------------------------------------------
// k2b: per-graph stats, 8 slices/graph (grid=2048). Partial reduce into
// g_stat via red.add.v4; last-arriving block per graph finalizes mean/rstd.
// ---------------------------------------------------------------------------
__global__ __launch_bounds__(256) void k2b_part(
    const int* __restrict__ batch, const float* __restrict__ gn_alpha, int N)
{
    int g     = blockIdx.x >> 3;
    int c4 = threadIdx.x & 15;
    int r  = threadIdx.x >> 4;
    int slice = blockIdx.x & 7;

    int lo = 0, hi = N;
    while (lo < hi) { int mid = (lo + hi) >> 1; if (batch[mid] < g) lo = mid + 1; else hi = mid; }
    int start = lo;
    lo = start; hi = N;
    while (lo < hi) { int mid = (lo + hi) >> 1; if (batch[mid] < g + 1) lo = mid + 1; else hi = mid; }
    int end = lo;

    const float4* h4 = reinterpret_cast<const float4*>(g_h);
    float4 s0 = make_float4(0.f, 0.f, 0.f, 0.f), q0 = s0;

    for (int i = start + slice * 16 + r; i < end; i += 128) {
        float4 a = h4[(size_t)i * 16 + c4];
        s0.x += a.x; s0.y += a.y; s0.z += a.z; s0.w += a.w;
        q0.x = fmaf(a.x, a.x, q0.x); q0.y = fmaf(a.y, a.y, q0.y);
        q0.z = fmaf(a.z, a.z, q0.z); q0.w = fmaf(a.w, a.w, q0.w);
    }

    __shared__ __align__(16) float4 sS[16][16];
    __shared__ __align__(16) float4 sQ[16][16];
    sS[r][c4] = s0;
    sQ[r][c4] = q0;
    __syncthreads();
    for (int off = 8; off > 0; off >>= 1) {
        if (r < off) {
            float4 a = sS[r][c4], b = sS[r + off][c4];
            sS[r][c4] = make_float4(a.x + b.x, a.y + b.y, a.z + b.z, a.w + b.w);
            float4 c = sQ[r][c4], d = sQ[r + off][c4];
            sQ[r][c4] = make_float4(c.x + d.x, c.y + d.y, c.z + d.z, c.w + d.w);
        }
        __syncthreads();
    }
    if (r == 0) {
        red_add_v4(&g_stat[g * 128 + c4 * 4], sS[0][c4]);
        red_add_v4(&g_stat[g * 128 + 64 + c4 * 4], sQ[0][c4]);
        __threadfence();
    }
    __syncthreads();
    __shared__ int slast;
    if (threadIdx.x == 0) slast = (atomicAdd(&g_k2b_ctr[g], 1) == 7) ? 1 : 0;
    __syncthreads();
    if (slast && threadIdx.x < 64) {
        __threadfence();
        int c = threadIdx.x;
        float cnt = fmaxf((float)(end - start), 1.0f);
        float rinv = 1.0f / cnt;
        float sum = g_stat[g * 128 + c];
        float sq  = g_stat[g * 128 + 64 + c];
        float mu = sum * rinv;
        float al = gn_alpha[c];
        float fac = 2.0f * al - al * al;
        float var = fmaxf(sq * rinv - fac * mu * mu, 0.0f);
        g_mean[g * 64 + c] = mu;
        g_rstd[g * 64 + c] = rsqrtf(var + EPS);
    }
}

// ---------------------------------------------------------------------------
// K3: finalize with fused channel attention (16-lane shfl reduction).
// ---------------------------------------------------------------------------
__device__ __forceinline__ float f4get(const float4& v, int u)
{
    switch (u) { case 0: return v.x; case 1: return v.y; case 2: return v.z; default: return v.w; }
}

__global__ __launch_bounds__(256) void k3_finalize(
    const float* __restrict__ x, const int* __restrict__ batch,
    const float* __restrict__ gnw, const float* __restrict__ gnb,
    const float* __restrict__ gna,
    const float* __restrict__ a1w, const float* __restrict__ a1b,
    const float* __restrict__ a2w, const float* __restrict__ a2b,
    float* __restrict__ out, int N)
{
    int i = blockIdx.x * blockDim.x + threadIdx.x;
    int n  = i >> 4;
    int c4 = i & 15;
    int g  = batch[n];

    float4 xv = reinterpret_cast<const float4*>(x)[(size_t)n * 16 + c4];

    float t[8];
#pragma unroll
    for (int r = 0; r < 8; r++) {
        float4 a1v = __ldg(reinterpret_cast<const float4*>(a1w) + r * 16 + c4);
        t[r] = xv.x * a1v.x + xv.y * a1v.y + xv.z * a1v.z + xv.w * a1v.w;
    }
#pragma unroll
    for (int m = 1; m < 16; m <<= 1) {
#pragma unroll
        for (int r = 0; r < 8; r++)
            t[r] += __shfl_xor_sync(0xffffffffu, t[r], m);
    }
#pragma unroll
    for (int r = 0; r < 8; r++) t[r] = fmaxf(t[r] + __ldg(a1b + r), 0.0f);

    float4 hv = reinterpret_cast<const float4*>(g_h)[(size_t)n * 16 + c4];
    float4 mu = reinterpret_cast<const float4*>(g_mean)[g * 16 + c4];
    float4 rs = reinterpret_cast<const float4*>(g_rstd)[g * 16 + c4];
    float4 al = __ldg(reinterpret_cast<const float4*>(gna) + c4);
    float4 w4 = __ldg(reinterpret_cast<const float4*>(gnw) + c4);
    float4 b4 = __ldg(reinterpret_cast<const float4*>(gnb) + c4);
    float4 b2 = __ldg(reinterpret_cast<const float4*>(a2b) + c4);

    float res[4];
#pragma unroll
    for (int u = 0; u < 4; u++) {
        int j = c4 * 4 + u;
        float4 wa = __ldg(reinterpret_cast<const float4*>(a2w) + j * 2);
        float4 wb = __ldg(reinterpret_cast<const float4*>(a2w) + j * 2 + 1);
        float z = wa.x * t[0] + wa.y * t[1] + wa.z * t[2] + wa.w * t[3]
                + wb.x * t[4] + wb.y * t[5] + wb.z * t[6] + wb.w * t[7]
                + f4get(b2, u);
        float gate = 1.0f / (1.0f + __expf(-z));
        float y = f4get(w4, u) * (f4get(hv, u) - f4get(mu, u) * f4get(al, u)) * f4get(rs, u)
                + f4get(b4, u);
        res[u] = fmaxf(y + gate * f4get(xv, u), 0.0f);
    }
    reinterpret_cast<float4*>(out)[(size_t)n * 16 + c4] =
        make_float4(res[0], res[1], res[2], res[3]);
}

// ---------------------------------------------------------------------------
// launch (6 kernels; 4th = k2_gemm, which the profiler captures)
// ---------------------------------------------------------------------------
extern "C" void kernel_launch(void* const* d_in, const int* in_sizes, int n_in,
                              void* d_out, int out_size)
{
    const float* x     = (const float*)d_in[0];
    const int*   ei    = (const int*)d_in[1];     // int32 (JAX x64 disabled)
    const int*   batch = (const int*)d_in[2];     // int32
    const float* Wl    = (const float*)d_in[3];
    const float* bl    = (const float*)d_in[4];
    const float* Wr    = (const float*)d_in[5];
    const float* gnw   = (const float*)d_in[6];
    const float* gnb   = (const float*)d_in[7];
    const float* gna   = (const float*)d_in[8];
    const float* a1w   = (const float*)d_in[9];
    const float* a1b   = (const float*)d_in[10];
    const float* a2w   = (const float*)d_in[11];
    const float* a2b   = (const float*)d_in[12];
    float*       out   = (float*)d_out;

    int N = in_sizes[0] / CC;          // 100000
    int E = in_sizes[1] / 2;           // 1200000
    int nb = (N + 255) / 256;          // 391 blocks (hist+scan)
    int ne4 = ((E + 3) / 4 + 255) / 256;  // kD, 4 edges/thread

    cudaFuncSetAttribute(k2_gemm, cudaFuncAttributeMaxDynamicSharedMemorySize,
                         K2_SMEM_BYTES);

    kHS<<<nb, 256>>>(ei, E, N);
    kD_place<<<ne4, 256>>>(ei, E, N);
    kE_gather<<<(N * 16 + 255) / 256, 256>>>(x, N);
    k2_gemm<<<(N + K2_TILE - 1) / K2_TILE, 256, K2_SMEM_BYTES>>>(x, Wl, bl, Wr, N);
    k2b_part<<<GG * 8, 256>>>(batch, gna, N);
    k3_finalize<<<(N * 16 + 255) / 256, 256>>>(x, batch, gnw, gnb, gna,
                                               a1w, a1b, a2w, a2b, out, N);
}

// round 17
// speedup vs baseline: 1.4327x; 1.0198x over previous
#include <cuda_runtime.h>
#include <cuda_bf16.h>
#include <stdint.h>

// Problem constants (fixed by the dataset)
#define NN 100000
#define CC 64
#define EE 1200000
#define GG 256
#define EPS 1e-5f

typedef unsigned long long u64;

#define FLAG_AGG (1ULL << 62)
#define FLAG_PRE (2ULL << 62)
#define VALMASK  ((1ULL << 62) - 1ULL)

// ---------------------------------------------------------------------------
// Scratch (device globals; loader zero-initialized; each call re-zeroes what
// it dirties AFTER last use so the graph stays deterministic).
// ---------------------------------------------------------------------------
__device__ __align__(16) float g_agg[NN * CC];    // neighbor-sum (gather output)
__device__ __align__(16) float g_deg[NN];         // in-degree (float)
__device__ __align__(16) float g_h[NN * CC];      // SAGE output
__device__ __align__(16) float g_mean[GG * CC];   // per-graph mean
__device__ __align__(16) float g_rstd[GG * CC];   // per-graph rsqrt(var+eps)
__device__ __align__(16) float g_stat[GG * 128];  // per-graph partial sum[64]|sq[64]

__device__ __align__(16) int g_cnt[NN];           // in-degree counts (zeroed by kD)
__device__ __align__(16) int g_off[NN + 1];       // CSR offsets
__device__ __align__(16) int g_cur[NN];           // placement cursors
__device__ __align__(16) int g_srcidx[EE];        // CSR: src node per slot
__device__ int g_k2b_ctr[GG];                     // last-block counters (zeroed by kE)
__device__ volatile u64 g_scanstate[512];         // lookback state (zeroed by kD)

__device__ __forceinline__ void red_add_v4(float* addr, float4 v)
{
    asm volatile("red.global.add.v4.f32 [%0], {%1, %2, %3, %4};"
                 :: "l"(addr), "f"(v.x), "f"(v.y), "f"(v.z), "f"(v.w)
                 : "memory");
}

// ---------------------------------------------------------------------------
// kB: histogram of in-degree. 4 edges/thread.
// ---------------------------------------------------------------------------
__global__ void kB_hist(const int* __restrict__ ei, int E)
{
    int base = (blockIdx.x * blockDim.x + threadIdx.x) * 4;
#pragma unroll
    for (int u = 0; u < 4; u++) {
        int e = base + u;
        if (e < E) atomicAdd(&g_cnt[ei[E + e]], 1);
    }
}

// ---------------------------------------------------------------------------
// kScan: single-pass exclusive scan of g_cnt -> g_off[N+1], g_cur
// (decoupled lookback, warp-parallel 32-wide windows)
// ---------------------------------------------------------------------------
__global__ __launch_bounds__(256) void kScan(int N)
{
    int b = blockIdx.x;
    int i = b * 256 + threadIdx.x;
    int lane = threadIdx.x & 31, w = threadIdx.x >> 5;

    int v = (i < N) ? g_cnt[i] : 0;
    int s = v;
#pragma unroll
    for (int o = 1; o < 32; o <<= 1) {
        int t = __shfl_up_sync(0xffffffffu, s, o);
        if (lane >= o) s += t;
    }
    __shared__ int wsum[8], woff[8], sbtot;
    __shared__ u64 sprefix;
    if (lane == 31) wsum[w] = s;
    __syncthreads();
    if (threadIdx.x == 0) {
        int acc = 0;
#pragma unroll
        for (int k = 0; k < 8; k++) { woff[k] = acc; acc += wsum[k]; }
        sbtot = acc;
        __threadfence();
        g_scanstate[b] = (b == 0 ? FLAG_PRE : FLAG_AGG) | (u64)acc;
        if (b == 0) sprefix = 0ULL;
    }
    __syncthreads();
    int incl = s + woff[w];
    int total = sbtot;

    if (b > 0 && w == 0) {
        long long run = 0;
        int base = b - 1;
        bool done = false;
        while (!done) {
            int idx = base - lane;
            u64 st = FLAG_PRE;
            if (idx >= 0) {
                do { st = g_scanstate[idx]; } while ((st >> 62) == 0ULL);
            }
            unsigned pre = __ballot_sync(0xffffffffu, (st >> 62) == 2ULL);
            long long val = (long long)(st & VALMASK);
            long long contrib;
            if (pre) {
                int firstpre = __ffs(pre) - 1;
                contrib = (lane <= firstpre) ? val : 0;
                done = true;
            } else {
                contrib = val;
            }
#pragma unroll
            for (int o = 16; o > 0; o >>= 1)
                contrib += __shfl_down_sync(0xffffffffu, contrib, o);
            contrib = __shfl_sync(0xffffffffu, contrib, 0);
            run += contrib;
            base -= 32;
        }
        if (lane == 0) {
            sprefix = (u64)run;
            __threadfence();
            g_scanstate[b] = FLAG_PRE | (u64)(run + (long long)total);
        }
    }
    __syncthreads();
    int P = (int)sprefix;
    if (i < N) {
        g_off[i + 1] = incl + P;
        g_cur[i]     = incl - v + P;
        if (i == 0) g_off[0] = 0;
    }
}

// ---------------------------------------------------------------------------
// kD: place src ids into CSR slots (4 edges/thread). Re-zeroes g_cnt and
// g_scanstate (fully consumed by kScan).
// ---------------------------------------------------------------------------
__global__ void kD_place(const int* __restrict__ ei, int E, int N)
{
    int t = blockIdx.x * blockDim.x + threadIdx.x;
    if (t < N)   g_cnt[t] = 0;
    if (t < 512) g_scanstate[t] = 0ULL;

    int base = t * 4;
#pragma unroll
    for (int u = 0; u < 4; u++) {
        int e = base + u;
        if (e < E) {
            int s = ei[e];
            int d = ei[E + e];
            int pos = atomicAdd(&g_cur[d], 1);
            g_srcidx[pos] = s;
        }
    }
}

// ---------------------------------------------------------------------------
// kE: gather-aggregate (proven config: unroll 2, 32 regs, occ ~74%).
// 16 threads per node; each owns one float4 channel group.
// Also zeroes g_stat / g_k2b_ctr for the k2b stage.
// ---------------------------------------------------------------------------
__global__ __launch_bounds__(256) void kE_gather(const float* __restrict__ x, int N)
{
    int gidx = blockIdx.x * 256 + threadIdx.x;
    if (gidx < GG * 32) reinterpret_cast<float4*>(g_stat)[gidx] = make_float4(0.f, 0.f, 0.f, 0.f);
    if (gidx < GG) g_k2b_ctr[gidx] = 0;

    int n  = gidx >> 4;
    int c4 = gidx & 15;
    if (n >= N) return;
    int off = g_off[n], end = g_off[n + 1];

    const float4* x4 = reinterpret_cast<const float4*>(x);
    float4 a0 = make_float4(0.f, 0.f, 0.f, 0.f);
    float4 a1 = a0;

    int k = off;
    for (; k + 1 < end; k += 2) {
        int s0 = g_srcidx[k];
        int s1 = g_srcidx[k + 1];
        float4 v0 = __ldg(x4 + (size_t)s0 * 16 + c4);
        float4 v1 = __ldg(x4 + (size_t)s1 * 16 + c4);
        a0.x += v0.x; a0.y += v0.y; a0.z += v0.z; a0.w += v0.w;
        a1.x += v1.x; a1.y += v1.y; a1.z += v1.z; a1.w += v1.w;
    }
    if (k < end) {
        int s0 = g_srcidx[k];
        float4 v0 = __ldg(x4 + (size_t)s0 * 16 + c4);
        a0.x += v0.x; a0.y += v0.y; a0.z += v0.z; a0.w += v0.w;
    }
    a0.x += a1.x; a0.y += a1.y; a0.z += a1.z; a0.w += a1.w;

    reinterpret_cast<float4*>(g_agg)[(size_t)n * 16 + c4] = a0;
    if (c4 == 0) g_deg[n] = (float)(end - off);
}

// ---------------------------------------------------------------------------
// K2: tiled GEMM with K-PANEL split for 3 blocks/SM occupancy:
//   h = [agg/deg | x] (N x 128) @ [Wl ; Wr] + bl
// Block: 128 nodes x 64 outputs, 256 threads; thread = 8 nodes x 4 outputs.
// Panels: p=0 uses agg/deg (k 0..63), p=1 uses x (k 64..127); sA is
// [64][128] (32KB) refilled between panels. sW [128][68] (34KB).
// Total smem 67,584 B -> 3 blocks/SM.
// ---------------------------------------------------------------------------
#define K2_TILE 128
#define SW_STRIDE 68
#define K2_SMEM_BYTES (64 * 128 * 4 + 128 * SW_STRIDE * 4)

__global__ __launch_bounds__(256) void k2_gemm(
    const float* __restrict__ x,
    const float* __restrict__ Wl, const float* __restrict__ bl,
    const float* __restrict__ Wr, int N)
{
    extern __shared__ float smem[];
    float* sA = smem;                 // [k 0..63][node 0..127] (per panel)
    float* sW = smem + 64 * 128;      // [k 0..127][j 0..63], row stride 68

    int tid = threadIdx.x;
    int n0 = blockIdx.x * K2_TILE;

    // weights: sW[k][j] = Wl[j][k]; sW[64+k][j] = Wr[j][k]
    for (int idx = tid; idx < 4096; idx += 256) {
        int j = idx >> 6, k = idx & 63;
        sW[k * SW_STRIDE + j] = __ldg(Wl + j * 64 + k);
        sW[(64 + k) * SW_STRIDE + j] = __ldg(Wr + j * 64 + k);
    }

    int tx = tid & 15;   // output quad: j = tx*4..tx*4+3
    int ty = tid >> 4;   // node group: nl = ty*8..ty*8+7
    int nl_f = tid & 127, half = tid >> 7;   // fill role: 2 thr/node, 8 c4 each
    int nf = n0 + nl_f; if (nf >= N) nf = N - 1;

    float acc[8][4];
    {
        float4 blv = __ldg(reinterpret_cast<const float4*>(bl) + tx);
#pragma unroll
        for (int i = 0; i < 8; i++) {
            acc[i][0] = blv.x; acc[i][1] = blv.y; acc[i][2] = blv.z; acc[i][3] = blv.w;
        }
    }

    float inv = 1.0f / fmaxf(g_deg[nf], 1.0f);
    const float4* ag4 = reinterpret_cast<const float4*>(g_agg) + (size_t)nf * 16;
    const float4* xx4 = reinterpret_cast<const float4*>(x) + (size_t)nf * 16;

#pragma unroll
    for (int p = 0; p < 2; p++) {
        // --- fill panel p: k-local 0..63 = channels 0..63 of (p? x : agg/deg)
#pragma unroll
        for (int i = 0; i < 8; i++) {
            int c4 = half * 8 + i;
            int kb = c4 * 4;
            float4 v;
            if (p == 0) {
                v = ag4[c4];
                v.x *= inv; v.y *= inv; v.z *= inv; v.w *= inv;
            } else {
                v = __ldg(xx4 + c4);
            }
            sA[(kb + 0) * 128 + nl_f] = v.x;
            sA[(kb + 1) * 128 + nl_f] = v.y;
            sA[(kb + 2) * 128 + nl_f] = v.z;
            sA[(kb + 3) * 128 + nl_f] = v.w;
        }
        __syncthreads();

        // --- MMA over this panel (weights rows p*64 .. p*64+63)
        const float* sWp = sW + p * 64 * SW_STRIDE;
#pragma unroll 4
        for (int k = 0; k < 64; k++) {
            float4 w  = *reinterpret_cast<const float4*>(&sWp[k * SW_STRIDE + tx * 4]);
            float4 a0 = *reinterpret_cast<const float4*>(&sA[k * 128 + ty * 8]);
            float4 a1 = *reinterpret_cast<const float4*>(&sA[k * 128 + ty * 8 + 4]);
            float av[8] = { a0.x, a0.y, a0.z, a0.w, a1.x, a1.y, a1.z, a1.w };
#pragma unroll
            for (int i = 0; i < 8; i++) {
                acc[i][0] = fmaf(av[i], w.x, acc[i][0]);
                acc[i][1] = fmaf(av[i], w.y, acc[i][1]);
                acc[i][2] = fmaf(av[i], w.z, acc[i][2]);
                acc[i][3] = fmaf(av[i], w.w, acc[i][3]);
            }
        }
        if (p == 0) __syncthreads();   // all reads done before refill
    }

    float4* h4 = reinterpret_cast<float4*>(g_h);
#pragma unroll
    for (int i = 0; i < 8; i++) {
        int n = n0 + ty * 8 + i;
        if (n < N)
            h4[(size_t)n * 16 + tx] = make_float4(acc[i][0], acc[i][1], acc[i][2], acc[i][3]);
    }
}

// ---------------------------------------------------------------------------
// k2b: per-graph stats, 8 slices/graph (grid=2048). Partial reduce into
// g_stat via red.add.v4; last-arriving block per graph finalizes mean/rstd.
// ---------------------------------------------------------------------------
__global__ __launch_bounds__(256) void k2b_part(
    const int* __restrict__ batch, const float* __restrict__ gn_alpha, int N)
{
    int g     = blockIdx.x >> 3;
    int c4 = threadIdx.x & 15;
    int r  = threadIdx.x >> 4;
    int slice = blockIdx.x & 7;

    int lo = 0, hi = N;
    while (lo < hi) { int mid = (lo + hi) >> 1; if (batch[mid] < g) lo = mid + 1; else hi = mid; }
    int start = lo;
    lo = start; hi = N;
    while (lo < hi) { int mid = (lo + hi) >> 1; if (batch[mid] < g + 1) lo = mid + 1; else hi = mid; }
    int end = lo;

    const float4* h4 = reinterpret_cast<const float4*>(g_h);
    float4 s0 = make_float4(0.f, 0.f, 0.f, 0.f), q0 = s0;

    for (int i = start + slice * 16 + r; i < end; i += 128) {
        float4 a = h4[(size_t)i * 16 + c4];
        s0.x += a.x; s0.y += a.y; s0.z += a.z; s0.w += a.w;
        q0.x = fmaf(a.x, a.x, q0.x); q0.y = fmaf(a.y, a.y, q0.y);
        q0.z = fmaf(a.z, a.z, q0.z); q0.w = fmaf(a.w, a.w, q0.w);
    }

    __shared__ __align__(16) float4 sS[16][16];
    __shared__ __align__(16) float4 sQ[16][16];
    sS[r][c4] = s0;
    sQ[r][c4] = q0;
    __syncthreads();
    for (int off = 8; off > 0; off >>= 1) {
        if (r < off) {
            float4 a = sS[r][c4], b = sS[r + off][c4];
            sS[r][c4] = make_float4(a.x + b.x, a.y + b.y, a.z + b.z, a.w + b.w);
            float4 c = sQ[r][c4], d = sQ[r + off][c4];
            sQ[r][c4] = make_float4(c.x + d.x, c.y + d.y, c.z + d.z, c.w + d.w);
        }
        __syncthreads();
    }
    if (r == 0) {
        red_add_v4(&g_stat[g * 128 + c4 * 4], sS[0][c4]);
        red_add_v4(&g_stat[g * 128 + 64 + c4 * 4], sQ[0][c4]);
        __threadfence();
    }
    __syncthreads();
    __shared__ int slast;
    if (threadIdx.x == 0) slast = (atomicAdd(&g_k2b_ctr[g], 1) == 7) ? 1 : 0;
    __syncthreads();
    if (slast && threadIdx.x < 64) {
        __threadfence();
        int c = threadIdx.x;
        float cnt = fmaxf((float)(end - start), 1.0f);
        float rinv = 1.0f / cnt;
        float sum = g_stat[g * 128 + c];
        float sq  = g_stat[g * 128 + 64 + c];
        float mu = sum * rinv;
        float al = gn_alpha[c];
        float fac = 2.0f * al - al * al;
        float var = fmaxf(sq * rinv - fac * mu * mu, 0.0f);
        g_mean[g * 64 + c] = mu;
        g_rstd[g * 64 + c] = rsqrtf(var + EPS);
    }
}

// ---------------------------------------------------------------------------
// K3: finalize with fused channel attention (16-lane shfl reduction).
// ---------------------------------------------------------------------------
__device__ __forceinline__ float f4get(const float4& v, int u)
{
    switch (u) { case 0: return v.x; case 1: return v.y; case 2: return v.z; default: return v.w; }
}

__global__ __launch_bounds__(256) void k3_finalize(
    const float* __restrict__ x, const int* __restrict__ batch,
    const float* __restrict__ gnw, const float* __restrict__ gnb,
    const float* __restrict__ gna,
    const float* __restrict__ a1w, const float* __restrict__ a1b,
    const float* __restrict__ a2w, const float* __restrict__ a2b,
    float* __restrict__ out, int N)
{
    int i = blockIdx.x * blockDim.x + threadIdx.x;
    int n  = i >> 4;
    int c4 = i & 15;
    int g  = batch[n];

    float4 xv = reinterpret_cast<const float4*>(x)[(size_t)n * 16 + c4];

    float t[8];
#pragma unroll
    for (int r = 0; r < 8; r++) {
        float4 a1v = __ldg(reinterpret_cast<const float4*>(a1w) + r * 16 + c4);
        t[r] = xv.x * a1v.x + xv.y * a1v.y + xv.z * a1v.z + xv.w * a1v.w;
    }
#pragma unroll
    for (int m = 1; m < 16; m <<= 1) {
#pragma unroll
        for (int r = 0; r < 8; r++)
            t[r] += __shfl_xor_sync(0xffffffffu, t[r], m);
    }
#pragma unroll
    for (int r = 0; r < 8; r++) t[r] = fmaxf(t[r] + __ldg(a1b + r), 0.0f);

    float4 hv = reinterpret_cast<const float4*>(g_h)[(size_t)n * 16 + c4];
    float4 mu = reinterpret_cast<const float4*>(g_mean)[g * 16 + c4];
    float4 rs = reinterpret_cast<const float4*>(g_rstd)[g * 16 + c4];
    float4 al = __ldg(reinterpret_cast<const float4*>(gna) + c4);
    float4 w4 = __ldg(reinterpret_cast<const float4*>(gnw) + c4);
    float4 b4 = __ldg(reinterpret_cast<const float4*>(gnb) + c4);
    float4 b2 = __ldg(reinterpret_cast<const float4*>(a2b) + c4);

    float res[4];
#pragma unroll
    for (int u = 0; u < 4; u++) {
        int j = c4 * 4 + u;
        float4 wa = __ldg(reinterpret_cast<const float4*>(a2w) + j * 2);
        float4 wb = __ldg(reinterpret_cast<const float4*>(a2w) + j * 2 + 1);
        float z = wa.x * t[0] + wa.y * t[1] + wa.z * t[2] + wa.w * t[3]
                + wb.x * t[4] + wb.y * t[5] + wb.z * t[6] + wb.w * t[7]
                + f4get(b2, u);
        float gate = 1.0f / (1.0f + __expf(-z));
        float y = f4get(w4, u) * (f4get(hv, u) - f4get(mu, u) * f4get(al, u)) * f4get(rs, u)
                + f4get(b4, u);
        res[u] = fmaxf(y + gate * f4get(xv, u), 0.0f);
    }
    reinterpret_cast<float4*>(out)[(size_t)n * 16 + c4] =
        make_float4(res[0], res[1], res[2], res[3]);
}

// ---------------------------------------------------------------------------
// launch (7 kernels)
// ---------------------------------------------------------------------------
extern "C" void kernel_launch(void* const* d_in, const int* in_sizes, int n_in,
                              void* d_out, int out_size)
{
    const float* x     = (const float*)d_in[0];
    const int*   ei    = (const int*)d_in[1];     // int32 (JAX x64 disabled)
    const int*   batch = (const int*)d_in[2];     // int32
    const float* Wl    = (const float*)d_in[3];
    const float* bl    = (const float*)d_in[4];
    const float* Wr    = (const float*)d_in[5];
    const float* gnw   = (const float*)d_in[6];
    const float* gnb   = (const float*)d_in[7];
    const float* gna   = (const float*)d_in[8];
    const float* a1w   = (const float*)d_in[9];
    const float* a1b   = (const float*)d_in[10];
    const float* a2w   = (const float*)d_in[11];
    const float* a2b   = (const float*)d_in[12];
    float*       out   = (float*)d_out;

    int N = in_sizes[0] / CC;          // 100000
    int E = in_sizes[1] / 2;           // 1200000
    int nb = (N + 255) / 256;          // 391 scan blocks
    int ne4 = ((E + 3) / 4 + 255) / 256;  // edge kernels, 4 edges/thread

    cudaFuncSetAttribute(k2_gemm, cudaFuncAttributeMaxDynamicSharedMemorySize,
                         K2_SMEM_BYTES);

    kB_hist<<<ne4, 256>>>(ei, E);
    kScan<<<nb, 256>>>(N);
    kD_place<<<ne4, 256>>>(ei, E, N);
    kE_gather<<<(N * 16 + 255) / 256, 256>>>(x, N);
    k2_gemm<<<(N + K2_TILE - 1) / K2_TILE, 256, K2_SMEM_BYTES>>>(x, Wl, bl, Wr, N);
    k2b_part<<<GG * 8, 256>>>(batch, gna, N);
    k3_finalize<<<(N * 16 + 255) / 256, 256>>>(x, batch, gnw, gnb, gna,
                                               a1w, a1b, a2w, a2b, out, N);
}